// round 15
// baseline (speedup 1.0000x reference)
#include <cuda_runtime.h>
#include <math.h>

#define NN   512
#define DD   128
#define M_TOTAL 2048   // 4*512

// Transposed scratch: [b][o][i]  (coalesced for column access)
__device__ float g_PbT[4 * DD * NN];   // (x@W1 - x@W2 + bias)^T
__device__ float g_QT [4 * DD * NN];   // (x@W2)^T

typedef unsigned long long ull;

static __device__ __forceinline__ ull pk2(float a) {      // {a, a}
    ull r; unsigned ai = __float_as_uint(a);
    asm("mov.b64 %0, {%1, %1};" : "=l"(r) : "r"(ai));
    return r;
}
static __device__ __forceinline__ ull fma2(ull a, ull b, ull c) {
    ull r; asm("fma.rn.f32x2 %0, %1, %2, %3;" : "=l"(r) : "l"(a), "l"(b), "l"(c));
    return r;
}

union F4U2 { float4 f4; ull u[2]; };
union U2F2 { ull u; float2 f2; };

static __device__ __forceinline__ void cpasync16(unsigned dst, const void* src) {
    asm volatile("cp.async.cg.shared.global [%0], [%1], 16;"
                 :: "r"(dst), "l"(src));
}
#define CP_COMMIT() asm volatile("cp.async.commit_group;")
#define CP_WAIT(n)  asm volatile("cp.async.wait_group %0;" :: "n"(n))

// ---------------------------------------------------------------------------
// Kernel 1: fused dual GEMM, outer-product form.
//   A1 = x@W1 ; Q = x@W2 ; PbT = (A1 - Q + bias)^T ; QT = Q^T
// grid 512 = (64 rowgroups of 32) x (8 colgroups of 16); 128 threads = 4 warps.
// Warp = 32 rows x 4 cols (lane = row). Per k per warp:
//   1 LDS.32 x (pad-129, conflict-free) + 2 bcast LDS.128 W + 4 FFMA2.
// Crossbar: 3 cyc / 4 FFMA2. 2048 warps total (13.8/SM).
// Epilogue: coalesced scalar stores into transposed PbT/QT.
// ---------------------------------------------------------------------------
__global__ __launch_bounds__(128)
void ec_gemm_kernel(const float* __restrict__ x,
                    const float* __restrict__ W,
                    const float* __restrict__ bias) {
    __shared__ float  xs[32 * 129];     // 16.5 KB, pad-129 (mainloop conflict-free)
    __shared__ float4 ws[128 * 8];      // 16 KB: [k][mat*4 + f]  (block's 16 cols)

    const int tid  = threadIdx.x;
    const int w    = tid >> 5;          // col-group within block (0..3)
    const int lane = tid & 31;          // row within 32
    const int rowBase = (blockIdx.x >> 3) * 32;
    const int cg   = blockIdx.x & 7;    // 16-col group
    const int c0   = cg * 16;

    const float4* __restrict__ W4 = (const float4*)W;

    // ---- stage W slice via cp.async: 1024 float4 (128 k x 4 f4 x 2 mats) ----
    {
        unsigned dst = (unsigned)__cvta_generic_to_shared(ws);
#pragma unroll
        for (int p = 0; p < 8; ++p) {
            const int idx = tid + p * 128;
            const int mat = idx >> 9;
            const int r   = idx & 511;
            const int k   = r >> 2;
            const int f   = r & 3;
            cpasync16(dst + (k * 8 + mat * 4 + f) * 16,
                      W4 + (size_t)(k + mat * DD) * 32 + cg * 4 + f);
        }
        CP_COMMIT();
    }

    // ---- stage x tile (coalesced LDG, scalar STS into pad-129) ----
    {
        const float4* x4 = (const float4*)(x + (size_t)rowBase * DD);
#pragma unroll
        for (int p = 0; p < 8; ++p) {
            const int idx = tid + p * 128;      // 0..1023
            const int row = idx >> 5;
            const int kq  = idx & 31;
            const float4 f = __ldg(&x4[idx]);
            float* d = &xs[row * 129 + kq * 4];
            d[0] = f.x; d[1] = f.y; d[2] = f.z; d[3] = f.w;
        }
    }
    CP_WAIT(0);
    __syncthreads();

    ull a1[2] = {0ull, 0ull};           // A1 cols (0,1),(2,3) of this warp
    ull qq[2] = {0ull, 0ull};

    const float* xr = &xs[lane * 129];

#pragma unroll 8
    for (int k = 0; k < DD; ++k) {
        const ull xp = pk2(xr[k]);                 // conflict-free LDS.32
        F4U2 w1, w2;
        w1.f4 = ws[k * 8 + w];                     // broadcast LDS.128
        w2.f4 = ws[k * 8 + 4 + w];
        a1[0] = fma2(xp, w1.u[0], a1[0]);
        a1[1] = fma2(xp, w1.u[1], a1[1]);
        qq[0] = fma2(xp, w2.u[0], qq[0]);
        qq[1] = fma2(xp, w2.u[1], qq[1]);
    }

    // ---- epilogue: transposed coalesced stores ----
    const int m = rowBase + lane;
    const int b = rowBase >> 9;
    const int i = m & 511;
    const float4 b4 = __ldg(&((const float4*)bias)[cg * 4 + w]);

    U2F2 A0, A1v, Q0, Q1;
    A0.u = a1[0]; A1v.u = a1[1]; Q0.u = qq[0]; Q1.u = qq[1];

    float Pv[4], Qv[4];
    Pv[0] = (A0.f2.x  - Q0.f2.x) + b4.x;  Qv[0] = Q0.f2.x;
    Pv[1] = (A0.f2.y  - Q0.f2.y) + b4.y;  Qv[1] = Q0.f2.y;
    Pv[2] = (A1v.f2.x - Q1.f2.x) + b4.z;  Qv[2] = Q1.f2.x;
    Pv[3] = (A1v.f2.y - Q1.f2.y) + b4.w;  Qv[3] = Q1.f2.y;

    const int c = c0 + w * 4;
#pragma unroll
    for (int u = 0; u < 4; ++u) {
        const size_t t = ((size_t)(b * DD + c + u) << 9) + i;   // [b][o][i]
        g_PbT[t] = Pv[u];                 // lanes -> consecutive i: coalesced
        g_QT [t] = Qv[u];
    }
}

// ---------------------------------------------------------------------------
// Kernel 2: fused column sort + probe.
// Block = one (b,o) column, 256 threads.
//  Phase A: bitonic sort (descending) of 512 keys (orderable(Q)<<32 | j).
//  Phase B: each thread probes 2 rows: first sorted candidate that is a
//           neighbor == exact masked max (exhaustion -> -inf -> relu 0).
// grid 512 x 256; 4 KB smem; all blocks co-resident (27.7 warps/SM).
// ---------------------------------------------------------------------------
__global__ __launch_bounds__(256)
void ec_sortprobe_kernel(const float* __restrict__ adj,
                         float* __restrict__ out) {
    __shared__ ull s[NN];

    const int tid = threadIdx.x;
    const int col = blockIdx.x;          // b*128 + o
    const int b   = col >> 7;
    const int o   = col & 127;

    // ---- load column (coalesced from QT) + orderable transform ----
    const float* __restrict__ Qc = g_QT + ((size_t)col << 9);
#pragma unroll
    for (int t = 0; t < 2; ++t) {
        const int j = tid + t * 256;
        const unsigned fb = __float_as_uint(__ldg(Qc + j));
        const unsigned u = (fb & 0x80000000u) ? ~fb : (fb | 0x80000000u);
        s[j] = ((ull)u << 32) | (unsigned)j;
    }
    __syncthreads();

    // ---- bitonic sort, descending (validated network) ----
    for (int k = 2; k <= NN; k <<= 1) {
        for (int j = k >> 1; j > 0; j >>= 1) {
            const int i = ((tid & ~(j - 1)) << 1) | (tid & (j - 1));
            const int q = i | j;
            const ull a = s[i];
            const ull c = s[q];
            const bool up = (i & k) == 0;
            const bool sw = up ? (a < c) : (a > c);
            if (sw) { s[i] = c; s[q] = a; }
            __syncthreads();
        }
    }

    // ---- probe: rows tid and tid+256 ----
    const float* __restrict__ adjb = adj + ((size_t)b << 18);  // b*512*512
    const int r0 = tid, r1 = tid + 256;

    float best0 = -3.0e38f, best1 = -3.0e38f;
    bool  d0 = false, d1 = false;

    for (int k = 0; k < NN; ++k) {
        const ull key = s[k];                    // broadcast LDS
        const int idx = (int)(key & 511u);
        if (!d0 && __ldg(adjb + ((size_t)r0 << 9) + idx) > 0.0f) {
            const unsigned u = (unsigned)(key >> 32);
            const unsigned fb = (u & 0x80000000u) ? (u ^ 0x80000000u) : ~u;
            best0 = __uint_as_float(fb);
            d0 = true;
        }
        if (!d1 && __ldg(adjb + ((size_t)r1 << 9) + idx) > 0.0f) {
            const unsigned u = (unsigned)(key >> 32);
            const unsigned fb = (u & 0x80000000u) ? (u ^ 0x80000000u) : ~u;
            best1 = __uint_as_float(fb);
            d1 = true;
        }
        if (__all_sync(0xffffffffu, d0 && d1)) break;
    }

    // ---- epilogue: PbT read coalesced; out scatter (fixed o) ----
    const float* __restrict__ Pc = g_PbT + ((size_t)col << 9);
    const float p0 = __ldg(Pc + r0);
    const float p1 = __ldg(Pc + r1);

    out[(size_t)(b * NN + r0) * DD + o] = fmaxf(0.0f, p0 + best0);
    out[(size_t)(b * NN + r1) * DD + o] = fmaxf(0.0f, p1 + best1);
}

// ---------------------------------------------------------------------------
extern "C" void kernel_launch(void* const* d_in, const int* in_sizes, int n_in,
                              void* d_out, int out_size) {
    const float* x    = (const float*)d_in[0];   // (4,512,128)
    const float* adj  = (const float*)d_in[1];   // (4,512,512)
    const float* W    = (const float*)d_in[2];   // (256,128)
    const float* bias = (const float*)d_in[3];   // (128,)
    float*       out  = (float*)d_out;           // (4,512,128)

    ec_gemm_kernel     <<<512, 128>>>(x, W, bias);
    ec_sortprobe_kernel<<<4 * DD, 256>>>(adj, out);
}

// round 16
// speedup vs baseline: 1.0061x; 1.0061x over previous
#include <cuda_runtime.h>
#include <math.h>

#define NN   512
#define DD   128
#define M_TOTAL 2048   // 4*512

// Transposed scratch: [b][o][i]  (coalesced for column access)
__device__ float g_PbT[4 * DD * NN];   // (x@W1 - x@W2 + bias)^T
__device__ float g_QT [4 * DD * NN];   // (x@W2)^T
__device__ unsigned g_adjbits[4][NN][16];   // packed adjacency rows (128 KB)

typedef unsigned long long ull;

static __device__ __forceinline__ ull pk2(float a) {      // {a, a}
    ull r; unsigned ai = __float_as_uint(a);
    asm("mov.b64 %0, {%1, %1};" : "=l"(r) : "r"(ai));
    return r;
}
static __device__ __forceinline__ ull fma2(ull a, ull b, ull c) {
    ull r; asm("fma.rn.f32x2 %0, %1, %2, %3;" : "=l"(r) : "l"(a), "l"(b), "l"(c));
    return r;
}

union F4U2 { float4 f4; ull u[2]; };
union U2F2 { ull u; float2 f2; };

static __device__ __forceinline__ void cpasync16(unsigned dst, const void* src) {
    asm volatile("cp.async.cg.shared.global [%0], [%1], 16;"
                 :: "r"(dst), "l"(src));
}
#define CP_COMMIT() asm volatile("cp.async.commit_group;")
#define CP_WAIT(n)  asm volatile("cp.async.wait_group %0;" :: "n"(n))

// ---------------------------------------------------------------------------
// Kernel 0: pack adj rows into bitmasks. Block = 8 rows (warp = row).
// ---------------------------------------------------------------------------
__global__ __launch_bounds__(256)
void ec_pack_kernel(const float* __restrict__ adj) {
    const int w    = threadIdx.x >> 5;
    const int lane = threadIdx.x & 31;
    const int row  = blockIdx.x * 8 + w;          // 0..2047

    const float* __restrict__ ar = adj + ((size_t)row << 9);
#pragma unroll
    for (int t = 0; t < 16; ++t) {
        const unsigned m =
            __ballot_sync(0xffffffffu, __ldg(ar + t * 32 + lane) > 0.0f);
        if (lane == 0) g_adjbits[row >> 9][row & 511][t] = m;
    }
}

// ---------------------------------------------------------------------------
// Kernel 1: fused dual GEMM, outer-product form (unchanged from R14).
// ---------------------------------------------------------------------------
__global__ __launch_bounds__(128)
void ec_gemm_kernel(const float* __restrict__ x,
                    const float* __restrict__ W,
                    const float* __restrict__ bias) {
    __shared__ float  xs[32 * 129];     // pad-129: mainloop conflict-free
    __shared__ float4 ws[128 * 8];      // [k][mat*4 + f] (block's 16 cols)

    const int tid  = threadIdx.x;
    const int w    = tid >> 5;
    const int lane = tid & 31;
    const int rowBase = (blockIdx.x >> 3) * 32;
    const int cg   = blockIdx.x & 7;
    const int c0   = cg * 16;

    const float4* __restrict__ W4 = (const float4*)W;

    {
        unsigned dst = (unsigned)__cvta_generic_to_shared(ws);
#pragma unroll
        for (int p = 0; p < 8; ++p) {
            const int idx = tid + p * 128;
            const int mat = idx >> 9;
            const int r   = idx & 511;
            const int k   = r >> 2;
            const int f   = r & 3;
            cpasync16(dst + (k * 8 + mat * 4 + f) * 16,
                      W4 + (size_t)(k + mat * DD) * 32 + cg * 4 + f);
        }
        CP_COMMIT();
    }

    {
        const float4* x4 = (const float4*)(x + (size_t)rowBase * DD);
#pragma unroll
        for (int p = 0; p < 8; ++p) {
            const int idx = tid + p * 128;
            const int row = idx >> 5;
            const int kq  = idx & 31;
            const float4 f = __ldg(&x4[idx]);
            float* d = &xs[row * 129 + kq * 4];
            d[0] = f.x; d[1] = f.y; d[2] = f.z; d[3] = f.w;
        }
    }
    CP_WAIT(0);
    __syncthreads();

    ull a1[2] = {0ull, 0ull};
    ull qq[2] = {0ull, 0ull};

    const float* xr = &xs[lane * 129];

#pragma unroll 8
    for (int k = 0; k < DD; ++k) {
        const ull xp = pk2(xr[k]);
        F4U2 w1, w2;
        w1.f4 = ws[k * 8 + w];
        w2.f4 = ws[k * 8 + 4 + w];
        a1[0] = fma2(xp, w1.u[0], a1[0]);
        a1[1] = fma2(xp, w1.u[1], a1[1]);
        qq[0] = fma2(xp, w2.u[0], qq[0]);
        qq[1] = fma2(xp, w2.u[1], qq[1]);
    }

    const int m = rowBase + lane;
    const int b = rowBase >> 9;
    const int i = m & 511;
    const float4 b4 = __ldg(&((const float4*)bias)[cg * 4 + w]);

    U2F2 A0, A1v, Q0, Q1;
    A0.u = a1[0]; A1v.u = a1[1]; Q0.u = qq[0]; Q1.u = qq[1];

    float Pv[4], Qv[4];
    Pv[0] = (A0.f2.x  - Q0.f2.x) + b4.x;  Qv[0] = Q0.f2.x;
    Pv[1] = (A0.f2.y  - Q0.f2.y) + b4.y;  Qv[1] = Q0.f2.y;
    Pv[2] = (A1v.f2.x - Q1.f2.x) + b4.z;  Qv[2] = Q1.f2.x;
    Pv[3] = (A1v.f2.y - Q1.f2.y) + b4.w;  Qv[3] = Q1.f2.y;

    const int c = c0 + w * 4;
#pragma unroll
    for (int u = 0; u < 4; ++u) {
        const size_t t = ((size_t)(b * DD + c + u) << 9) + i;
        g_PbT[t] = Pv[u];
        g_QT [t] = Qv[u];
    }
}

// ---------------------------------------------------------------------------
// Kernel 2: fused column sort + BITMASK probe.
// Block = one (b,o) column, 256 threads.
//  Phase A: load batch bitmask (32 KB, coalesced) + bitonic sort 512 keys.
//  Phase B: thread probes rows tid / tid+256 against smem bitmask:
//           first sorted candidate that is a neighbor == exact masked max.
// smem 39 KB static; bitmask padded x17 words -> probe is bank-conflict-free.
// ---------------------------------------------------------------------------
__global__ __launch_bounds__(256)
void ec_sortprobe_kernel(float* __restrict__ out) {
    __shared__ ull      s[NN];           // 4 KB keys
    __shared__ unsigned bits[NN * 17];   // 34 KB padded bitmasks

    const int tid = threadIdx.x;
    const int col = blockIdx.x;          // b*128 + o
    const int b   = col >> 7;
    const int o   = col & 127;

    // ---- load bitmask rows (2 rows/thread, coalesced 16B loads) ----
    {
        const uint4* __restrict__ src = (const uint4*)&g_adjbits[b][0][0];
#pragma unroll
        for (int t = 0; t < 2; ++t) {
            const int r = tid + t * 256;
#pragma unroll
            for (int q = 0; q < 4; ++q) {
                const uint4 v = __ldg(src + r * 4 + q);
                unsigned* d = &bits[r * 17 + q * 4];
                d[0] = v.x; d[1] = v.y; d[2] = v.z; d[3] = v.w;
            }
        }
    }

    // ---- load Q column (coalesced from QT) + orderable transform ----
    const float* __restrict__ Qc = g_QT + ((size_t)col << 9);
#pragma unroll
    for (int t = 0; t < 2; ++t) {
        const int j = tid + t * 256;
        const unsigned fb = __float_as_uint(__ldg(Qc + j));
        const unsigned u = (fb & 0x80000000u) ? ~fb : (fb | 0x80000000u);
        s[j] = ((ull)u << 32) | (unsigned)j;
    }
    __syncthreads();

    // ---- bitonic sort, descending (validated network) ----
    for (int k = 2; k <= NN; k <<= 1) {
        for (int j = k >> 1; j > 0; j >>= 1) {
            const int i = ((tid & ~(j - 1)) << 1) | (tid & (j - 1));
            const int q = i | j;
            const ull a = s[i];
            const ull c = s[q];
            const bool up = (i & k) == 0;
            const bool sw = up ? (a < c) : (a > c);
            if (sw) { s[i] = c; s[q] = a; }
            __syncthreads();
        }
    }

    // ---- probe rows tid and tid+256 against smem bitmask ----
    const int r0 = tid, r1 = tid + 256;
    ull  k0 = 0, k1 = 0;
    bool d0 = false, d1 = false;

    for (int k = 0; k < NN; ++k) {
        const ull key = s[k];                    // broadcast LDS
        const int idx = (int)(key & 511u);
        const int wd  = idx >> 5;
        const unsigned bit = 1u << (idx & 31);
        if (!d0 && (bits[r0 * 17 + wd] & bit)) { k0 = key; d0 = true; }
        if (!d1 && (bits[r1 * 17 + wd] & bit)) { k1 = key; d1 = true; }
        if (__all_sync(0xffffffffu, d0 && d1)) break;
    }

    float best0 = -3.0e38f, best1 = -3.0e38f;
    if (d0) {
        const unsigned u = (unsigned)(k0 >> 32);
        best0 = __uint_as_float((u & 0x80000000u) ? (u ^ 0x80000000u) : ~u);
    }
    if (d1) {
        const unsigned u = (unsigned)(k1 >> 32);
        best1 = __uint_as_float((u & 0x80000000u) ? (u ^ 0x80000000u) : ~u);
    }

    // ---- epilogue ----
    const float* __restrict__ Pc = g_PbT + ((size_t)col << 9);
    const float p0 = __ldg(Pc + r0);
    const float p1 = __ldg(Pc + r1);

    out[(size_t)(b * NN + r0) * DD + o] = fmaxf(0.0f, p0 + best0);
    out[(size_t)(b * NN + r1) * DD + o] = fmaxf(0.0f, p1 + best1);
}

// ---------------------------------------------------------------------------
extern "C" void kernel_launch(void* const* d_in, const int* in_sizes, int n_in,
                              void* d_out, int out_size) {
    const float* x    = (const float*)d_in[0];   // (4,512,128)
    const float* adj  = (const float*)d_in[1];   // (4,512,512)
    const float* W    = (const float*)d_in[2];   // (256,128)
    const float* bias = (const float*)d_in[3];   // (128,)
    float*       out  = (float*)d_out;           // (4,512,128)

    ec_pack_kernel     <<<256, 256>>>(adj);
    ec_gemm_kernel     <<<512, 128>>>(x, W, bias);
    ec_sortprobe_kernel<<<4 * DD, 256>>>(out);
}

// round 17
// speedup vs baseline: 1.0281x; 1.0218x over previous
#include <cuda_runtime.h>
#include <math.h>

#define NN   512
#define DD   128
#define M_TOTAL 2048   // 4*512

// Transposed scratch: [b][o][i]  (coalesced for column access)
__device__ float g_PbT[4 * DD * NN];   // (x@W1 - x@W2 + bias)^T
__device__ float g_QT [4 * DD * NN];   // (x@W2)^T
__device__ unsigned g_adjbits[4][NN][16];   // packed adjacency rows (128 KB)

typedef unsigned long long ull;

static __device__ __forceinline__ ull pk2(float a) {      // {a, a}
    ull r; unsigned ai = __float_as_uint(a);
    asm("mov.b64 %0, {%1, %1};" : "=l"(r) : "r"(ai));
    return r;
}
static __device__ __forceinline__ ull fma2(ull a, ull b, ull c) {
    ull r; asm("fma.rn.f32x2 %0, %1, %2, %3;" : "=l"(r) : "l"(a), "l"(b), "l"(c));
    return r;
}

union F4U2 { float4 f4; ull u[2]; };
union U2F2 { ull u; float2 f2; };

static __device__ __forceinline__ void cpasync16(unsigned dst, const void* src) {
    asm volatile("cp.async.cg.shared.global [%0], [%1], 16;"
                 :: "r"(dst), "l"(src));
}
#define CP_COMMIT() asm volatile("cp.async.commit_group;")
#define CP_WAIT(n)  asm volatile("cp.async.wait_group %0;" :: "n"(n))

// ---------------------------------------------------------------------------
// Kernel 1: FUSED pack + dual GEMM.
// grid 512 x 256 threads.
//   blocks [0,256):   GEMM. Block = 32 rows x 32 cols (2 col-groups of 16,
//                     one per 128-thr sub, SHARING one x tile). Outer-product:
//                     per k per warp: 1 LDS.32 x + 2 bcast LDS.128 W + 4 FFMA2.
//   blocks [256,512): PACK. Warp = adj row; 16 batched LDGs (MLP=16) then
//                     16 ballots -> g_adjbits. Runs concurrently with GEMM.
// ---------------------------------------------------------------------------
__global__ __launch_bounds__(256)
void ec_fused1_kernel(const float* __restrict__ x,
                      const float* __restrict__ W,
                      const float* __restrict__ bias,
                      const float* __restrict__ adj) {
    __shared__ float  xs[32 * 129];     // 16.5 KB pad-129
    __shared__ float4 ws[2][1024];      // 2 x 16 KB: [k][mat*4 + f] per sub

    const int tid = threadIdx.x;

    if (blockIdx.x >= 256) {
        // ---------------- PACK ----------------
        const int p    = blockIdx.x - 256;
        const int w    = tid >> 5;
        const int lane = tid & 31;
        const int row  = p * 8 + w;              // 0..2047

        const float* __restrict__ ar = adj + ((size_t)row << 9);
        float v[16];
#pragma unroll
        for (int t = 0; t < 16; ++t) v[t] = __ldg(ar + t * 32 + lane);
#pragma unroll
        for (int t = 0; t < 16; ++t) {
            const unsigned m = __ballot_sync(0xffffffffu, v[t] > 0.0f);
            if (lane == 0) g_adjbits[row >> 9][row & 511][t] = m;
        }
        return;
    }

    // ---------------- GEMM ----------------
    const int rg   = blockIdx.x >> 2;    // row group (0..63)
    const int cgp  = blockIdx.x & 3;     // col-group pair (0..3)
    const int sub  = tid >> 7;           // 0/1: which 16-col group
    const int tid1 = tid & 127;
    const int w    = tid1 >> 5;
    const int lane = tid1 & 31;
    const int rowBase = rg * 32;
    const int cg   = cgp * 2 + sub;      // 16-col group (0..7)

    const float4* __restrict__ W4 = (const float4*)W;

    // stage this sub's W slice (1024 float4) via cp.async
    {
        unsigned dst = (unsigned)__cvta_generic_to_shared(&ws[sub][0]);
#pragma unroll
        for (int p = 0; p < 8; ++p) {
            const int idx = tid1 + p * 128;
            const int mat = idx >> 9;
            const int r   = idx & 511;
            const int k   = r >> 2;
            const int f   = r & 3;
            cpasync16(dst + (k * 8 + mat * 4 + f) * 16,
                      W4 + (size_t)(k + mat * DD) * 32 + cg * 4 + f);
        }
        CP_COMMIT();
    }

    // stage x tile (shared by both subs): 1024 float4, 4 per thread
    {
        const float4* x4 = (const float4*)(x + (size_t)rowBase * DD);
#pragma unroll
        for (int p = 0; p < 4; ++p) {
            const int idx = tid + p * 256;
            const int row = idx >> 5;
            const int kq  = idx & 31;
            const float4 f = __ldg(&x4[idx]);
            float* d = &xs[row * 129 + kq * 4];
            d[0] = f.x; d[1] = f.y; d[2] = f.z; d[3] = f.w;
        }
    }
    CP_WAIT(0);
    __syncthreads();

    ull a1[2] = {0ull, 0ull};
    ull qq[2] = {0ull, 0ull};

    const float* xr = &xs[lane * 129];
    const float4* wsub = &ws[sub][0];

#pragma unroll 8
    for (int k = 0; k < DD; ++k) {
        const ull xp = pk2(xr[k]);                 // conflict-free LDS.32
        F4U2 w1, w2;
        w1.f4 = wsub[k * 8 + w];                   // broadcast LDS.128
        w2.f4 = wsub[k * 8 + 4 + w];
        a1[0] = fma2(xp, w1.u[0], a1[0]);
        a1[1] = fma2(xp, w1.u[1], a1[1]);
        qq[0] = fma2(xp, w2.u[0], qq[0]);
        qq[1] = fma2(xp, w2.u[1], qq[1]);
    }

    // epilogue: transposed coalesced stores
    const int m = rowBase + lane;
    const int b = rowBase >> 9;
    const int i = m & 511;
    const float4 b4 = __ldg(&((const float4*)bias)[cg * 4 + w]);

    U2F2 A0, A1v, Q0, Q1;
    A0.u = a1[0]; A1v.u = a1[1]; Q0.u = qq[0]; Q1.u = qq[1];

    float Pv[4], Qv[4];
    Pv[0] = (A0.f2.x  - Q0.f2.x) + b4.x;  Qv[0] = Q0.f2.x;
    Pv[1] = (A0.f2.y  - Q0.f2.y) + b4.y;  Qv[1] = Q0.f2.y;
    Pv[2] = (A1v.f2.x - Q1.f2.x) + b4.z;  Qv[2] = Q1.f2.x;
    Pv[3] = (A1v.f2.y - Q1.f2.y) + b4.w;  Qv[3] = Q1.f2.y;

    const int c = cg * 16 + w * 4;
#pragma unroll
    for (int u = 0; u < 4; ++u) {
        const size_t t = ((size_t)(b * DD + c + u) << 9) + i;
        g_PbT[t] = Pv[u];
        g_QT [t] = Qv[u];
    }
}

// ---------------------------------------------------------------------------
// Kernel 2: fused sort + bitmask probe, 2 COLUMNS PER BLOCK.
// grid 256 x 512 threads. sub = tid>>8 owns column blockIdx*2 + sub.
// bits load (34 KB) and the 45 sort barriers amortized over 2 column-sorts.
// Probe: thread -> rows stid / stid+256 of its sub's column; first sorted
// candidate that is a neighbor == exact masked max (exhaustion -> relu 0).
// ---------------------------------------------------------------------------
__global__ __launch_bounds__(512)
void ec_sortprobe_kernel(float* __restrict__ out) {
    __shared__ ull      s[2][NN];        // 8 KB keys (one sort per sub)
    __shared__ unsigned bits[NN * 17];   // 34 KB padded bitmasks (shared)

    const int tid  = threadIdx.x;
    const int sub  = tid >> 8;
    const int stid = tid & 255;
    const int col  = blockIdx.x * 2 + sub;   // b*128 + o
    const int b    = col >> 7;               // same b for both subs
    const int o    = col & 127;

    // ---- load bitmask rows (1 row/thread, coalesced 16B loads) ----
    {
        const uint4* __restrict__ src = (const uint4*)&g_adjbits[b][0][0];
        const int r = tid;                   // 0..511
#pragma unroll
        for (int q = 0; q < 4; ++q) {
            const uint4 v = __ldg(src + r * 4 + q);
            unsigned* d = &bits[r * 17 + q * 4];
            d[0] = v.x; d[1] = v.y; d[2] = v.z; d[3] = v.w;
        }
    }

    // ---- load Q column (coalesced from QT) + orderable transform ----
    const float* __restrict__ Qc = g_QT + ((size_t)col << 9);
#pragma unroll
    for (int t = 0; t < 2; ++t) {
        const int j = stid + t * 256;
        const unsigned fb = __float_as_uint(__ldg(Qc + j));
        const unsigned u = (fb & 0x80000000u) ? ~fb : (fb | 0x80000000u);
        s[sub][j] = ((ull)u << 32) | (unsigned)j;
    }
    __syncthreads();

    // ---- bitonic sort, descending (validated network), per sub ----
    for (int k = 2; k <= NN; k <<= 1) {
        for (int j = k >> 1; j > 0; j >>= 1) {
            const int i = ((stid & ~(j - 1)) << 1) | (stid & (j - 1));
            const int q = i | j;
            const ull a = s[sub][i];
            const ull c = s[sub][q];
            const bool up = (i & k) == 0;
            const bool sw = up ? (a < c) : (a > c);
            if (sw) { s[sub][i] = c; s[sub][q] = a; }
            __syncthreads();
        }
    }

    // ---- probe rows stid and stid+256 against smem bitmask ----
    const int r0 = stid, r1 = stid + 256;
    ull  k0 = 0, k1 = 0;
    bool d0 = false, d1 = false;

    for (int k = 0; k < NN; ++k) {
        const ull key = s[sub][k];               // broadcast LDS
        const int idx = (int)(key & 511u);
        const int wd  = idx >> 5;
        const unsigned bit = 1u << (idx & 31);
        if (!d0 && (bits[r0 * 17 + wd] & bit)) { k0 = key; d0 = true; }
        if (!d1 && (bits[r1 * 17 + wd] & bit)) { k1 = key; d1 = true; }
        if (__all_sync(0xffffffffu, d0 && d1)) break;   // warps are sub-pure
    }

    float best0 = -3.0e38f, best1 = -3.0e38f;
    if (d0) {
        const unsigned u = (unsigned)(k0 >> 32);
        best0 = __uint_as_float((u & 0x80000000u) ? (u ^ 0x80000000u) : ~u);
    }
    if (d1) {
        const unsigned u = (unsigned)(k1 >> 32);
        best1 = __uint_as_float((u & 0x80000000u) ? (u ^ 0x80000000u) : ~u);
    }

    // ---- epilogue ----
    const float* __restrict__ Pc = g_PbT + ((size_t)col << 9);
    const float p0 = __ldg(Pc + r0);
    const float p1 = __ldg(Pc + r1);

    out[(size_t)(b * NN + r0) * DD + o] = fmaxf(0.0f, p0 + best0);
    out[(size_t)(b * NN + r1) * DD + o] = fmaxf(0.0f, p1 + best1);
}

// ---------------------------------------------------------------------------
extern "C" void kernel_launch(void* const* d_in, const int* in_sizes, int n_in,
                              void* d_out, int out_size) {
    const float* x    = (const float*)d_in[0];   // (4,512,128)
    const float* adj  = (const float*)d_in[1];   // (4,512,512)
    const float* W    = (const float*)d_in[2];   // (256,128)
    const float* bias = (const float*)d_in[3];   // (128,)
    float*       out  = (float*)d_out;           // (4,512,128)

    ec_fused1_kernel   <<<512, 256>>>(x, W, bias, adj);
    ec_sortprobe_kernel<<<256, 512>>>(out);
}